// round 1
// baseline (speedup 1.0000x reference)
#include <cuda_runtime.h>
#include <math.h>
#include <stdint.h>

#define BSZ     2
#define LSEQ    2048
#define DMODEL  1024
#define DINNER  2048
#define NSTATE  16
#define KCONV   4
#define NTOK    (BSZ*LSEQ)   // 4096

// ---------------- scratch (static device globals; no allocation) -------------
__device__ float g_h   [NTOK*DMODEL];   // post-LN
__device__ float g_xs  [NTOK*DINNER];   // GEMM1 out, x-branch (pre-conv)
__device__ float g_gate[NTOK*DINNER];   // GEMM1 out, gate branch
__device__ float g_xc  [NTOK*DINNER];   // conv+silu out; later overwritten by y
__device__ float g_dsum[NTOK];          // row sums of softplus
__device__ float g_dA  [NTOK*NSTATE];
__device__ float g_Bx  [NTOK*NSTATE];
__device__ float g_hs  [NTOK*NSTATE];

// ---------------- small utils ------------------------------------------------
__global__ void zero_delta_kernel() {
    int i = blockIdx.x * blockDim.x + threadIdx.x;
    if (i < NTOK) g_dsum[i] = 0.f;
}

// ---------------- layernorm --------------------------------------------------
__global__ __launch_bounds__(256) void ln_kernel(const float* __restrict__ x,
                                                 const float* __restrict__ gamma,
                                                 const float* __restrict__ beta) {
    int row = blockIdx.x;
    const float* xr = x + (size_t)row * DMODEL;
    float v[4];
    float s = 0.f, s2 = 0.f;
#pragma unroll
    for (int i = 0; i < 4; i++) {
        v[i] = xr[threadIdx.x + i * 256];
        s  += v[i];
        s2 += v[i] * v[i];
    }
    // block reduce (8 warps)
    __shared__ float shs[8], shs2[8];
#pragma unroll
    for (int off = 16; off > 0; off >>= 1) {
        s  += __shfl_xor_sync(0xffffffffu, s,  off);
        s2 += __shfl_xor_sync(0xffffffffu, s2, off);
    }
    int warp = threadIdx.x >> 5, lane = threadIdx.x & 31;
    if (lane == 0) { shs[warp] = s; shs2[warp] = s2; }
    __syncthreads();
    if (threadIdx.x == 0) {
        float a = 0.f, b = 0.f;
#pragma unroll
        for (int w = 0; w < 8; w++) { a += shs[w]; b += shs2[w]; }
        shs[0] = a; shs2[0] = b;
    }
    __syncthreads();
    float mu  = shs[0]  * (1.f / DMODEL);
    float var = shs2[0] * (1.f / DMODEL) - mu * mu;
    float rs  = rsqrtf(var + 1e-5f);
    float* hr = g_h + (size_t)row * DMODEL;
#pragma unroll
    for (int i = 0; i < 4; i++) {
        int idx = threadIdx.x + i * 256;
        hr[idx] = (v[i] - mu) * rs * gamma[idx] + beta[idx];
    }
}

// ---------------- generic tiled SGEMM, 128x128x8, 8x8 per thread ------------
// EPI 0: split columns -> g_xs (col<2048) / g_gate (col-2048)
// EPI 1: softplus(acc+bias[col]) row-summed into g_dsum (no C write)
// EPI 2: C0[row*N+col] = acc + extra[row*N+col]
template <int EPI>
__global__ __launch_bounds__(256) void gemm_kernel(const float* __restrict__ A,
                                                   const float* __restrict__ Bm,
                                                   float* __restrict__ C0,
                                                   float* __restrict__ C1,
                                                   const float* __restrict__ extra,
                                                   const float* __restrict__ bias,
                                                   int M, int N, int K) {
    __shared__ __align__(16) float As[8 * 128];
    __shared__ __align__(16) float Bs[8 * 128];
    int bc = blockIdx.x, br = blockIdx.y;
    int tid = threadIdx.x;
    int tx = tid & 15, ty = tid >> 4;

    float acc[8][8];
#pragma unroll
    for (int i = 0; i < 8; i++)
#pragma unroll
        for (int j = 0; j < 8; j++) acc[i][j] = 0.f;

    const float* Ablk = A + (size_t)(br * 128) * K;
    const float* Bblk = Bm + bc * 128;
    int a_r = tid >> 1, a_c = (tid & 1) * 4;
    int b_r = tid >> 5, b_c = (tid & 31) * 4;

    for (int kk = 0; kk < K; kk += 8) {
        float4 av = *(const float4*)(Ablk + (size_t)a_r * K + kk + a_c);
        float4 bv = *(const float4*)(Bblk + (size_t)(kk + b_r) * N + b_c);
        As[(a_c + 0) * 128 + a_r] = av.x;
        As[(a_c + 1) * 128 + a_r] = av.y;
        As[(a_c + 2) * 128 + a_r] = av.z;
        As[(a_c + 3) * 128 + a_r] = av.w;
        *(float4*)(Bs + b_r * 128 + b_c) = bv;
        __syncthreads();
#pragma unroll
        for (int k = 0; k < 8; k++) {
            float ra[8], rb[8];
            *(float4*)(ra)     = *(const float4*)(As + k * 128 + ty * 8);
            *(float4*)(ra + 4) = *(const float4*)(As + k * 128 + ty * 8 + 4);
            *(float4*)(rb)     = *(const float4*)(Bs + k * 128 + tx * 8);
            *(float4*)(rb + 4) = *(const float4*)(Bs + k * 128 + tx * 8 + 4);
#pragma unroll
            for (int i = 0; i < 8; i++)
#pragma unroll
                for (int j = 0; j < 8; j++)
                    acc[i][j] = fmaf(ra[i], rb[j], acc[i][j]);
        }
        __syncthreads();
    }

    int row0 = br * 128 + ty * 8;
    int col0 = bc * 128 + tx * 8;

    if (EPI == 0) {
        // split into xs / gate (each N/2 = 2048 wide); block is wholly one side
        bool left = (col0 < DINNER);
        float* dst = left ? g_xs : g_gate;
        int cbase = left ? col0 : (col0 - DINNER);
#pragma unroll
        for (int i = 0; i < 8; i++) {
            float* p = dst + (size_t)(row0 + i) * DINNER + cbase;
            *(float4*)(p)     = make_float4(acc[i][0], acc[i][1], acc[i][2], acc[i][3]);
            *(float4*)(p + 4) = make_float4(acc[i][4], acc[i][5], acc[i][6], acc[i][7]);
        }
    } else if (EPI == 1) {
        float bb[8];
#pragma unroll
        for (int j = 0; j < 8; j++) bb[j] = bias[col0 + j];
#pragma unroll
        for (int i = 0; i < 8; i++) {
            float s = 0.f;
#pragma unroll
            for (int j = 0; j < 8; j++) {
                float v = acc[i][j] + bb[j];
                float sp = (v > 20.f) ? v : log1pf(expf(v));
                s += sp;
            }
            atomicAdd(&g_dsum[row0 + i], s);
        }
    } else {
#pragma unroll
        for (int i = 0; i < 8; i++) {
            const float* xr = extra + (size_t)(row0 + i) * N + col0;
            float* p = C0 + (size_t)(row0 + i) * N + col0;
            float4 r0 = *(const float4*)(xr);
            float4 r1 = *(const float4*)(xr + 4);
            *(float4*)(p)     = make_float4(acc[i][0] + r0.x, acc[i][1] + r0.y,
                                            acc[i][2] + r0.z, acc[i][3] + r0.w);
            *(float4*)(p + 4) = make_float4(acc[i][4] + r1.x, acc[i][5] + r1.y,
                                            acc[i][6] + r1.z, acc[i][7] + r1.w);
        }
    }
}

// ---------------- depthwise causal conv (K=4) + SiLU ------------------------
__global__ __launch_bounds__(256) void conv_silu_kernel(const float* __restrict__ w,
                                                        const float* __restrict__ cb) {
    int id = blockIdx.x * 256 + threadIdx.x;          // over B*L*DINNER
    int d = id & (DINNER - 1);
    int rest = id >> 11;                               // /2048
    int l = rest & (LSEQ - 1);
    int b = rest >> 11;
    const float* wr = w + d * KCONV;
    float v = cb[d];
#pragma unroll
    for (int k = 0; k < KCONV; k++) {
        int ll = l - (KCONV - 1) + k;
        float xv = (ll >= 0) ? g_xs[((size_t)(b * LSEQ + ll)) * DINNER + d] : 0.f;
        v = fmaf(wr[k], xv, v);
    }
    float sv = v / (1.f + expf(-v));                   // silu
    g_xc[(size_t)id] = sv;
}

// ---------------- Bx = (xc @ B^T) * delta ; dA = exp(delta*A) ----------------
__global__ __launch_bounds__(256) void bx_kernel(const float* __restrict__ Bmat,
                                                 const float* __restrict__ A_log) {
    int t = blockIdx.x;                                // token 0..4095
    const float* xrow = g_xc + (size_t)t * DINNER;
    float xr[8];
#pragma unroll
    for (int i = 0; i < 8; i++) xr[i] = xrow[threadIdx.x + i * 256];

    float part[NSTATE];
#pragma unroll
    for (int n = 0; n < NSTATE; n++) {
        const float* Brow = Bmat + n * DINNER;
        float s = 0.f;
#pragma unroll
        for (int i = 0; i < 8; i++)
            s = fmaf(xr[i], Brow[threadIdx.x + i * 256], s);
        part[n] = s;
    }
    // warp reduce each n
#pragma unroll
    for (int n = 0; n < NSTATE; n++)
#pragma unroll
        for (int off = 16; off > 0; off >>= 1)
            part[n] += __shfl_xor_sync(0xffffffffu, part[n], off);

    __shared__ float sh[NSTATE][8];
    int warp = threadIdx.x >> 5, lane = threadIdx.x & 31;
    if (lane == 0)
#pragma unroll
        for (int n = 0; n < NSTATE; n++) sh[n][warp] = part[n];
    __syncthreads();

    if (threadIdx.x < NSTATE) {
        int n = threadIdx.x;
        float tot = 0.f;
#pragma unroll
        for (int w = 0; w < 8; w++) tot += sh[n][w];
        float delta = g_dsum[t] * (1.f / DINNER);
        float An = -expf(A_log[n]);
        g_dA[t * NSTATE + n] = expf(delta * An);
        g_Bx[t * NSTATE + n] = tot * delta;
    }
}

// ---------------- parallel linear-recurrence scan ----------------------------
// one block per (b,n); 256 threads x 8 elements each; h_l = a_l*h_{l-1} + b_l
__global__ __launch_bounds__(256) void scan_kernel() {
    int bn = blockIdx.x;
    int b = bn >> 4, n = bn & 15;
    size_t base = (size_t)b * LSEQ * NSTATE + n;
    int tid = threadIdx.x;
    int l0 = tid * 8;

    float av[8], bv[8];
#pragma unroll
    for (int i = 0; i < 8; i++) {
        av[i] = g_dA[base + (size_t)(l0 + i) * NSTATE];
        bv[i] = g_Bx[base + (size_t)(l0 + i) * NSTATE];
    }
    // local composite: (aL, bL)
    float aL = 1.f, bL = 0.f;
#pragma unroll
    for (int i = 0; i < 8; i++) { bL = fmaf(av[i], bL, bv[i]); aL *= av[i]; }

    __shared__ float sa[256], sb[256];
    sa[tid] = aL; sb[tid] = bL;
    __syncthreads();
#pragma unroll
    for (int off = 1; off < 256; off <<= 1) {
        float pa = 1.f, pb = 0.f;
        if (tid >= off) { pa = sa[tid - off]; pb = sb[tid - off]; }
        float ca = sa[tid], cb2 = sb[tid];
        __syncthreads();
        sa[tid] = pa * ca;
        sb[tid] = fmaf(pb, ca, cb2);
        __syncthreads();
    }
    float hprev = (tid == 0) ? 0.f : sb[tid - 1];
    float h = hprev;
#pragma unroll
    for (int i = 0; i < 8; i++) {
        h = fmaf(av[i], h, bv[i]);
        g_hs[base + (size_t)(l0 + i) * NSTATE] = h;
    }
}

// ---------------- y = (hs@C^T + D*xc) * silu(gate), in place into g_xc -------
__global__ __launch_bounds__(256) void ymix_kernel(const float* __restrict__ Cmat,
                                                   const float* __restrict__ Dv) {
    int t = blockIdx.x;
    __shared__ float hsh[NSTATE];
    if (threadIdx.x < NSTATE) hsh[threadIdx.x] = g_hs[t * NSTATE + threadIdx.x];
    __syncthreads();

    for (int d = threadIdx.x; d < DINNER; d += 256) {
        const float4* cr = (const float4*)(Cmat + (size_t)d * NSTATE);
        float4 c0 = cr[0], c1 = cr[1], c2 = cr[2], c3 = cr[3];
        float s = 0.f;
        s = fmaf(hsh[0],  c0.x, s); s = fmaf(hsh[1],  c0.y, s);
        s = fmaf(hsh[2],  c0.z, s); s = fmaf(hsh[3],  c0.w, s);
        s = fmaf(hsh[4],  c1.x, s); s = fmaf(hsh[5],  c1.y, s);
        s = fmaf(hsh[6],  c1.z, s); s = fmaf(hsh[7],  c1.w, s);
        s = fmaf(hsh[8],  c2.x, s); s = fmaf(hsh[9],  c2.y, s);
        s = fmaf(hsh[10], c2.z, s); s = fmaf(hsh[11], c2.w, s);
        s = fmaf(hsh[12], c3.x, s); s = fmaf(hsh[13], c3.y, s);
        s = fmaf(hsh[14], c3.z, s); s = fmaf(hsh[15], c3.w, s);
        size_t idx = (size_t)t * DINNER + d;
        float xv = g_xc[idx];
        float yv = fmaf(Dv[d], xv, s);
        float g = g_gate[idx];
        yv *= g / (1.f + expf(-g));
        g_xc[idx] = yv;
    }
}

// ---------------- launch -----------------------------------------------------
extern "C" void kernel_launch(void* const* d_in, const int* in_sizes, int n_in,
                              void* d_out, int out_size) {
    const float* x       = (const float*)d_in[0];
    const float* ln_g    = (const float*)d_in[1];
    const float* ln_b    = (const float*)d_in[2];
    const float* W_in    = (const float*)d_in[3];
    const float* conv_w  = (const float*)d_in[4];
    const float* conv_b  = (const float*)d_in[5];
    const float* A_log   = (const float*)d_in[6];
    const float* B_mat   = (const float*)d_in[7];
    const float* C_mat   = (const float*)d_in[8];
    const float* D_vec   = (const float*)d_in[9];
    const float* Wd      = (const float*)d_in[10];
    const float* bd      = (const float*)d_in[11];
    const float* W_out   = (const float*)d_in[12];
    float* out           = (float*)d_out;

    // fetch device symbol addresses for GEMM A operands
    float* hptr;  cudaGetSymbolAddress((void**)&hptr,  g_h);
    float* xcptr; cudaGetSymbolAddress((void**)&xcptr, g_xc);

    zero_delta_kernel<<<16, 256>>>();
    ln_kernel<<<NTOK, 256>>>(x, ln_g, ln_b);
    // GEMM1: h(4096x1024) @ W_in(1024x4096) -> xs | gate
    gemm_kernel<0><<<dim3(32, 32), 256>>>(hptr, W_in, nullptr, nullptr, nullptr, nullptr,
                                          NTOK, 2 * DINNER, DMODEL);
    conv_silu_kernel<<<(NTOK * DINNER) / 256, 256>>>(conv_w, conv_b);
    // GEMM2: xc(4096x2048) @ Wd(2048x2048), softplus row-sum epilogue
    gemm_kernel<1><<<dim3(16, 32), 256>>>(xcptr, Wd, nullptr, nullptr, nullptr, bd,
                                          NTOK, DINNER, DINNER);
    bx_kernel<<<NTOK, 256>>>(B_mat, A_log);
    scan_kernel<<<BSZ * NSTATE, 256>>>();
    ymix_kernel<<<NTOK, 256>>>(C_mat, D_vec);
    // GEMM3: y(4096x2048) @ W_out(2048x1024) + residual -> out
    gemm_kernel<2><<<dim3(8, 32), 256>>>(xcptr, W_out, out, nullptr, x, nullptr,
                                         NTOK, DMODEL, DINNER);
}

// round 3
// speedup vs baseline: 3.0986x; 3.0986x over previous
#include <cuda_runtime.h>
#include <math.h>
#include <stdint.h>

#define BSZ     2
#define LSEQ    2048
#define DMODEL  1024
#define DINNER  2048
#define NSTATE  16
#define KCONV   4
#define NTOK    (BSZ*LSEQ)   // 4096

// ---------------- scratch (static device globals; no allocation) -------------
__device__ float g_h   [NTOK*DMODEL];
__device__ float g_xs  [NTOK*DINNER];
__device__ float g_gate[NTOK*DINNER];
__device__ float g_xc  [NTOK*DINNER];
__device__ float g_dsum[NTOK];
__device__ float g_dA  [NTOK*NSTATE];
__device__ float g_Bx  [NTOK*NSTATE];
__device__ float g_hs  [NTOK*NSTATE];

// ---------------- helpers ----------------------------------------------------
__device__ __forceinline__ uint32_t smem_u32(const void* p) {
    uint32_t a;
    asm("{ .reg .u64 t; cvta.to.shared.u64 t, %1; cvt.u32.u64 %0, t; }" : "=r"(a) : "l"(p));
    return a;
}
__device__ __forceinline__ uint32_t tf32r(float x) {
    uint32_t u; asm("cvt.rna.tf32.f32 %0, %1;" : "=r"(u) : "f"(x)); return u;
}
__device__ __forceinline__ void cp16(uint32_t saddr, const void* g) {
    asm volatile("cp.async.cg.shared.global [%0], [%1], 16;" :: "r"(saddr), "l"(g) : "memory");
}
#define CP_COMMIT() asm volatile("cp.async.commit_group;" ::: "memory")

__device__ __forceinline__ void mma_tf32(float& c0, float& c1, float& c2, float& c3,
                                         uint32_t a0, uint32_t a1, uint32_t a2, uint32_t a3,
                                         uint32_t b0, uint32_t b1) {
    asm volatile("mma.sync.aligned.m16n8k8.row.col.f32.tf32.tf32.f32 "
                 "{%0,%1,%2,%3}, {%4,%5,%6,%7}, {%8,%9}, {%0,%1,%2,%3};"
                 : "+f"(c0), "+f"(c1), "+f"(c2), "+f"(c3)
                 : "r"(a0), "r"(a1), "r"(a2), "r"(a3), "r"(b0), "r"(b1));
}

// ---------------- small utils ------------------------------------------------
__global__ void zero_delta_kernel() {
    int i = blockIdx.x * blockDim.x + threadIdx.x;
    if (i < NTOK) g_dsum[i] = 0.f;
}

// ---------------- layernorm --------------------------------------------------
__global__ __launch_bounds__(256) void ln_kernel(const float* __restrict__ x,
                                                 const float* __restrict__ gamma,
                                                 const float* __restrict__ beta) {
    int row = blockIdx.x;
    const float* xr = x + (size_t)row * DMODEL;
    float v[4];
    float s = 0.f, s2 = 0.f;
#pragma unroll
    for (int i = 0; i < 4; i++) {
        v[i] = xr[threadIdx.x + i * 256];
        s  += v[i];
        s2 += v[i] * v[i];
    }
    __shared__ float shs[8], shs2[8];
#pragma unroll
    for (int off = 16; off > 0; off >>= 1) {
        s  += __shfl_xor_sync(0xffffffffu, s,  off);
        s2 += __shfl_xor_sync(0xffffffffu, s2, off);
    }
    int warp = threadIdx.x >> 5, lane = threadIdx.x & 31;
    if (lane == 0) { shs[warp] = s; shs2[warp] = s2; }
    __syncthreads();
    if (threadIdx.x == 0) {
        float a = 0.f, b = 0.f;
#pragma unroll
        for (int w = 0; w < 8; w++) { a += shs[w]; b += shs2[w]; }
        shs[0] = a; shs2[0] = b;
    }
    __syncthreads();
    float mu  = shs[0]  * (1.f / DMODEL);
    float var = shs2[0] * (1.f / DMODEL) - mu * mu;
    float rs  = rsqrtf(var + 1e-5f);
    float* hr = g_h + (size_t)row * DMODEL;
#pragma unroll
    for (int i = 0; i < 4; i++) {
        int idx = threadIdx.x + i * 256;
        hr[idx] = (v[i] - mu) * rs * gamma[idx] + beta[idx];
    }
}

// ---------------- TF32 mma.sync GEMM -----------------------------------------
// Block 128x128, 8 warps (2 row x 4 col), warp tile 64x32, K-chunk 32,
// cp.async double-buffered SMEM. A: [128][36] row-major. B: [32][136] row-major.
// EPI 0: split cols -> g_xs / g_gate
// EPI 1: softplus(acc+bias) row-sum -> atomicAdd g_dsum (no C write)
// EPI 2: C0 = acc + extra (residual)
#define A_STRIDE 36
#define B_STRIDE 136
#define A_BUF (128 * A_STRIDE)      // 4608 floats
#define B_BUF (32 * B_STRIDE)       // 4352 floats
#define GSMEM_BYTES ((2 * A_BUF + 2 * B_BUF) * 4)   // 71680

template <int EPI>
__global__ __launch_bounds__(256) void mma_gemm(const float* __restrict__ A,
                                                const float* __restrict__ Bm,
                                                float* __restrict__ C0,
                                                const float* __restrict__ extra,
                                                const float* __restrict__ bias,
                                                int M, int N, int K) {
    extern __shared__ float dsm[];
    uint32_t sb = smem_u32(dsm);

    int tid = threadIdx.x;
    int lane = tid & 31, wid = tid >> 5;
    int warp_m = wid & 1, warp_n = wid >> 1;
    int br = blockIdx.y, bc = blockIdx.x;

    const float* Ab = A + (size_t)(br * 128) * K;
    const float* Bb = Bm + bc * 128;

    // per-thread copy coordinates
    int a_row = tid >> 1, a_c4 = (tid & 1) * 16;         // 2 float4 per thread? no:
    // A chunk: 128x32 = 1024 float4; 256 thr -> 4 each: idx = tid + i*256, row=idx>>3, c4=idx&7
    // B chunk: 32x128 = 1024 float4; idx = tid + i*256, kr=idx>>5, n4=idx&31
    (void)a_row; (void)a_c4;

    float acc[4][4][4];
#pragma unroll
    for (int mf = 0; mf < 4; mf++)
#pragma unroll
        for (int nf = 0; nf < 4; nf++)
#pragma unroll
            for (int j = 0; j < 4; j++) acc[mf][nf][j] = 0.f;

    int niter = K / 32;

    // prologue: copy chunk 0 into buffer 0
    {
        int it = 0;
        uint32_t sa = sb;                       // A0
        uint32_t sbf = sb + (2 * A_BUF) * 4;    // B0
#pragma unroll
        for (int i = 0; i < 4; i++) {
            int idx = tid + i * 256;
            int row = idx >> 3, c4 = idx & 7;
            cp16(sa + (row * A_STRIDE + c4 * 4) * 4, Ab + (size_t)row * K + it * 32 + c4 * 4);
        }
#pragma unroll
        for (int i = 0; i < 4; i++) {
            int idx = tid + i * 256;
            int kr = idx >> 5, n4 = idx & 31;
            cp16(sbf + (kr * B_STRIDE + n4 * 4) * 4, Bb + (size_t)(it * 32 + kr) * N + n4 * 4);
        }
        CP_COMMIT();
    }

    for (int it = 0; it < niter; ++it) {
        if (it + 1 < niter) {
            int nb = (it + 1) & 1;
            uint32_t sa = sb + (nb ? A_BUF * 4 : 0);
            uint32_t sbf = sb + (2 * A_BUF + (nb ? B_BUF : 0)) * 4;
#pragma unroll
            for (int i = 0; i < 4; i++) {
                int idx = tid + i * 256;
                int row = idx >> 3, c4 = idx & 7;
                cp16(sa + (row * A_STRIDE + c4 * 4) * 4,
                     Ab + (size_t)row * K + (it + 1) * 32 + c4 * 4);
            }
#pragma unroll
            for (int i = 0; i < 4; i++) {
                int idx = tid + i * 256;
                int kr = idx >> 5, n4 = idx & 31;
                cp16(sbf + (kr * B_STRIDE + n4 * 4) * 4,
                     Bb + (size_t)((it + 1) * 32 + kr) * N + n4 * 4);
            }
            CP_COMMIT();
            asm volatile("cp.async.wait_group 1;" ::: "memory");
        } else {
            asm volatile("cp.async.wait_group 0;" ::: "memory");
        }
        __syncthreads();

        int cb = it & 1;
        const float* As = dsm + (cb ? A_BUF : 0);
        const float* Bs = dsm + 2 * A_BUF + (cb ? B_BUF : 0);
        int g = lane >> 2, t4 = lane & 3;

#pragma unroll
        for (int ks = 0; ks < 4; ks++) {
            int k0 = ks * 8;
            uint32_t afr[4][4];
#pragma unroll
            for (int mf = 0; mf < 4; mf++) {
                int r0 = warp_m * 64 + mf * 16;
                afr[mf][0] = tf32r(As[(r0 + g) * A_STRIDE + k0 + t4]);
                afr[mf][1] = tf32r(As[(r0 + 8 + g) * A_STRIDE + k0 + t4]);
                afr[mf][2] = tf32r(As[(r0 + g) * A_STRIDE + k0 + 4 + t4]);
                afr[mf][3] = tf32r(As[(r0 + 8 + g) * A_STRIDE + k0 + 4 + t4]);
            }
            uint32_t bfr[4][2];
#pragma unroll
            for (int nf = 0; nf < 4; nf++) {
                int c0 = warp_n * 32 + nf * 8;
                bfr[nf][0] = tf32r(Bs[(k0 + t4) * B_STRIDE + c0 + g]);
                bfr[nf][1] = tf32r(Bs[(k0 + 4 + t4) * B_STRIDE + c0 + g]);
            }
#pragma unroll
            for (int mf = 0; mf < 4; mf++)
#pragma unroll
                for (int nf = 0; nf < 4; nf++)
                    mma_tf32(acc[mf][nf][0], acc[mf][nf][1], acc[mf][nf][2], acc[mf][nf][3],
                             afr[mf][0], afr[mf][1], afr[mf][2], afr[mf][3],
                             bfr[nf][0], bfr[nf][1]);
        }
        __syncthreads();
    }

    // -------- epilogue --------
    int g = lane >> 2, t4 = lane & 3;
#pragma unroll
    for (int mf = 0; mf < 4; mf++) {
        int row0 = br * 128 + warp_m * 64 + mf * 16 + g;
        if (EPI == 1) {
            float sum0 = 0.f, sum1 = 0.f;
#pragma unroll
            for (int nf = 0; nf < 4; nf++) {
                int col = bc * 128 + warp_n * 32 + nf * 8 + 2 * t4;
                float b0 = bias[col], b1 = bias[col + 1];
                float v;
                v = acc[mf][nf][0] + b0; sum0 += (v > 20.f) ? v : log1pf(expf(v));
                v = acc[mf][nf][1] + b1; sum0 += (v > 20.f) ? v : log1pf(expf(v));
                v = acc[mf][nf][2] + b0; sum1 += (v > 20.f) ? v : log1pf(expf(v));
                v = acc[mf][nf][3] + b1; sum1 += (v > 20.f) ? v : log1pf(expf(v));
            }
#pragma unroll
            for (int off = 1; off < 4; off <<= 1) {
                sum0 += __shfl_xor_sync(0xffffffffu, sum0, off);
                sum1 += __shfl_xor_sync(0xffffffffu, sum1, off);
            }
            if (t4 == 0) {
                atomicAdd(&g_dsum[row0], sum0);
                atomicAdd(&g_dsum[row0 + 8], sum1);
            }
        } else if (EPI == 0) {
            bool left = (bc * 128 < DINNER);
            float* dst = left ? g_xs : g_gate;
            int cbase = bc * 128 - (left ? 0 : DINNER) + warp_n * 32;
#pragma unroll
            for (int nf = 0; nf < 4; nf++) {
                int col = cbase + nf * 8 + 2 * t4;
                *(float2*)(dst + (size_t)row0 * DINNER + col) =
                    make_float2(acc[mf][nf][0], acc[mf][nf][1]);
                *(float2*)(dst + (size_t)(row0 + 8) * DINNER + col) =
                    make_float2(acc[mf][nf][2], acc[mf][nf][3]);
            }
        } else {
#pragma unroll
            for (int nf = 0; nf < 4; nf++) {
                int col = bc * 128 + warp_n * 32 + nf * 8 + 2 * t4;
                float2 e0 = *(const float2*)(extra + (size_t)row0 * N + col);
                float2 e1 = *(const float2*)(extra + (size_t)(row0 + 8) * N + col);
                *(float2*)(C0 + (size_t)row0 * N + col) =
                    make_float2(acc[mf][nf][0] + e0.x, acc[mf][nf][1] + e0.y);
                *(float2*)(C0 + (size_t)(row0 + 8) * N + col) =
                    make_float2(acc[mf][nf][2] + e1.x, acc[mf][nf][3] + e1.y);
            }
        }
    }
}

// ---------------- depthwise causal conv (K=4) + SiLU ------------------------
__global__ __launch_bounds__(256) void conv_silu_kernel(const float* __restrict__ w,
                                                        const float* __restrict__ cb) {
    int id = blockIdx.x * 256 + threadIdx.x;
    int d = id & (DINNER - 1);
    int rest = id >> 11;
    int l = rest & (LSEQ - 1);
    int b = rest >> 11;
    const float* wr = w + d * KCONV;
    float v = cb[d];
#pragma unroll
    for (int k = 0; k < KCONV; k++) {
        int ll = l - (KCONV - 1) + k;
        float xv = (ll >= 0) ? g_xs[((size_t)(b * LSEQ + ll)) * DINNER + d] : 0.f;
        v = fmaf(wr[k], xv, v);
    }
    g_xc[(size_t)id] = v / (1.f + expf(-v));
}

// ---------------- Bx / dA ----------------------------------------------------
__global__ __launch_bounds__(256) void bx_kernel(const float* __restrict__ Bmat,
                                                 const float* __restrict__ A_log) {
    int t = blockIdx.x;
    const float* xrow = g_xc + (size_t)t * DINNER;
    float xr[8];
#pragma unroll
    for (int i = 0; i < 8; i++) xr[i] = xrow[threadIdx.x + i * 256];

    float part[NSTATE];
#pragma unroll
    for (int n = 0; n < NSTATE; n++) {
        const float* Brow = Bmat + n * DINNER;
        float s = 0.f;
#pragma unroll
        for (int i = 0; i < 8; i++)
            s = fmaf(xr[i], Brow[threadIdx.x + i * 256], s);
        part[n] = s;
    }
#pragma unroll
    for (int n = 0; n < NSTATE; n++)
#pragma unroll
        for (int off = 16; off > 0; off >>= 1)
            part[n] += __shfl_xor_sync(0xffffffffu, part[n], off);

    __shared__ float sh[NSTATE][8];
    int warp = threadIdx.x >> 5, lane = threadIdx.x & 31;
    if (lane == 0)
#pragma unroll
        for (int n = 0; n < NSTATE; n++) sh[n][warp] = part[n];
    __syncthreads();

    if (threadIdx.x < NSTATE) {
        int n = threadIdx.x;
        float tot = 0.f;
#pragma unroll
        for (int w = 0; w < 8; w++) tot += sh[n][w];
        float delta = g_dsum[t] * (1.f / DINNER);
        float An = -expf(A_log[n]);
        g_dA[t * NSTATE + n] = expf(delta * An);
        g_Bx[t * NSTATE + n] = tot * delta;
    }
}

// ---------------- parallel linear-recurrence scan ----------------------------
__global__ __launch_bounds__(256) void scan_kernel() {
    int bn = blockIdx.x;
    int b = bn >> 4, n = bn & 15;
    size_t base = (size_t)b * LSEQ * NSTATE + n;
    int tid = threadIdx.x;
    int l0 = tid * 8;

    float av[8], bv[8];
#pragma unroll
    for (int i = 0; i < 8; i++) {
        av[i] = g_dA[base + (size_t)(l0 + i) * NSTATE];
        bv[i] = g_Bx[base + (size_t)(l0 + i) * NSTATE];
    }
    float aL = 1.f, bL = 0.f;
#pragma unroll
    for (int i = 0; i < 8; i++) { bL = fmaf(av[i], bL, bv[i]); aL *= av[i]; }

    __shared__ float sa[256], sbm[256];
    sa[tid] = aL; sbm[tid] = bL;
    __syncthreads();
#pragma unroll
    for (int off = 1; off < 256; off <<= 1) {
        float pa = 1.f, pb = 0.f;
        if (tid >= off) { pa = sa[tid - off]; pb = sbm[tid - off]; }
        float ca = sa[tid], cb2 = sbm[tid];
        __syncthreads();
        sa[tid] = pa * ca;
        sbm[tid] = fmaf(pb, ca, cb2);
        __syncthreads();
    }
    float h = (tid == 0) ? 0.f : sbm[tid - 1];
#pragma unroll
    for (int i = 0; i < 8; i++) {
        h = fmaf(av[i], h, bv[i]);
        g_hs[base + (size_t)(l0 + i) * NSTATE] = h;
    }
}

// ---------------- y = (hs@C^T + D*xc) * silu(gate) ---------------------------
__global__ __launch_bounds__(256) void ymix_kernel(const float* __restrict__ Cmat,
                                                   const float* __restrict__ Dv) {
    int t = blockIdx.x;
    __shared__ float hsh[NSTATE];
    if (threadIdx.x < NSTATE) hsh[threadIdx.x] = g_hs[t * NSTATE + threadIdx.x];
    __syncthreads();

    for (int d = threadIdx.x; d < DINNER; d += 256) {
        const float4* cr = (const float4*)(Cmat + (size_t)d * NSTATE);
        float4 c0 = cr[0], c1 = cr[1], c2 = cr[2], c3 = cr[3];
        float s = 0.f;
        s = fmaf(hsh[0],  c0.x, s); s = fmaf(hsh[1],  c0.y, s);
        s = fmaf(hsh[2],  c0.z, s); s = fmaf(hsh[3],  c0.w, s);
        s = fmaf(hsh[4],  c1.x, s); s = fmaf(hsh[5],  c1.y, s);
        s = fmaf(hsh[6],  c1.z, s); s = fmaf(hsh[7],  c1.w, s);
        s = fmaf(hsh[8],  c2.x, s); s = fmaf(hsh[9],  c2.y, s);
        s = fmaf(hsh[10], c2.z, s); s = fmaf(hsh[11], c2.w, s);
        s = fmaf(hsh[12], c3.x, s); s = fmaf(hsh[13], c3.y, s);
        s = fmaf(hsh[14], c3.z, s); s = fmaf(hsh[15], c3.w, s);
        size_t idx = (size_t)t * DINNER + d;
        float xv = g_xc[idx];
        float yv = fmaf(Dv[d], xv, s);
        float g = g_gate[idx];
        yv *= g / (1.f + expf(-g));
        g_xc[idx] = yv;
    }
}

// ---------------- launch -----------------------------------------------------
extern "C" void kernel_launch(void* const* d_in, const int* in_sizes, int n_in,
                              void* d_out, int out_size) {
    const float* x       = (const float*)d_in[0];
    const float* ln_g    = (const float*)d_in[1];
    const float* ln_b    = (const float*)d_in[2];
    const float* W_in    = (const float*)d_in[3];
    const float* conv_w  = (const float*)d_in[4];
    const float* conv_b  = (const float*)d_in[5];
    const float* A_log   = (const float*)d_in[6];
    const float* B_mat   = (const float*)d_in[7];
    const float* C_mat   = (const float*)d_in[8];
    const float* D_vec   = (const float*)d_in[9];
    const float* Wd      = (const float*)d_in[10];
    const float* bd      = (const float*)d_in[11];
    const float* W_out   = (const float*)d_in[12];
    float* out           = (float*)d_out;

    float* hptr;  cudaGetSymbolAddress((void**)&hptr,  g_h);
    float* xcptr; cudaGetSymbolAddress((void**)&xcptr, g_xc);

    cudaFuncSetAttribute(mma_gemm<0>, cudaFuncAttributeMaxDynamicSharedMemorySize, GSMEM_BYTES);
    cudaFuncSetAttribute(mma_gemm<1>, cudaFuncAttributeMaxDynamicSharedMemorySize, GSMEM_BYTES);
    cudaFuncSetAttribute(mma_gemm<2>, cudaFuncAttributeMaxDynamicSharedMemorySize, GSMEM_BYTES);

    zero_delta_kernel<<<16, 256>>>();
    ln_kernel<<<NTOK, 256>>>(x, ln_g, ln_b);
    // GEMM1: h(4096x1024) @ W_in(1024x4096) -> xs | gate
    mma_gemm<0><<<dim3(32, 32), 256, GSMEM_BYTES>>>(hptr, W_in, nullptr, nullptr, nullptr,
                                                    NTOK, 2 * DINNER, DMODEL);
    conv_silu_kernel<<<(NTOK * DINNER) / 256, 256>>>(conv_w, conv_b);
    // GEMM2: xc(4096x2048) @ Wd(2048x2048), softplus row-sum epilogue
    mma_gemm<1><<<dim3(16, 32), 256, GSMEM_BYTES>>>(xcptr, Wd, nullptr, nullptr, bd,
                                                    NTOK, DINNER, DINNER);
    bx_kernel<<<NTOK, 256>>>(B_mat, A_log);
    scan_kernel<<<BSZ * NSTATE, 256>>>();
    ymix_kernel<<<NTOK, 256>>>(C_mat, D_vec);
    // GEMM3: y(4096x2048) @ W_out(2048x1024) + residual -> out
    mma_gemm<2><<<dim3(8, 32), 256, GSMEM_BYTES>>>(xcptr, W_out, out, x, nullptr,
                                                   NTOK, DMODEL, DINNER);
}

// round 4
// speedup vs baseline: 4.8659x; 1.5703x over previous
#include <cuda_runtime.h>
#include <cuda_bf16.h>
#include <math.h>
#include <stdint.h>

#define BSZ     2
#define LSEQ    2048
#define DMODEL  1024
#define DINNER  2048
#define NSTATE  16
#define KCONV   4
#define NTOK    (BSZ*LSEQ)   // 4096

// ---------------- scratch (static device globals; no allocation) -------------
__device__ __align__(256) __nv_bfloat16 g_hbf   [NTOK*DMODEL];
__device__ __align__(256) __nv_bfloat16 g_xsbf  [NTOK*DINNER];
__device__ __align__(256) __nv_bfloat16 g_gatebf[NTOK*DINNER];
__device__ __align__(256) __nv_bfloat16 g_xcbf  [NTOK*DINNER];
__device__ __align__(256) __nv_bfloat16 g_ybf   [NTOK*DINNER];
__device__ __align__(256) __nv_bfloat16 g_Wint  [(2*DINNER)*DMODEL];  // W_in^T  [4096][1024]
__device__ __align__(256) __nv_bfloat16 g_Wdt   [DINNER*DINNER];      // Wd^T    [2048][2048]
__device__ __align__(256) __nv_bfloat16 g_Woutt [DMODEL*DINNER];      // W_out^T [1024][2048]
__device__ float g_dsum[NTOK];
__device__ float g_dA  [NTOK*NSTATE];
__device__ float g_Bx  [NTOK*NSTATE];
__device__ float g_hs  [NTOK*NSTATE];

// ---------------- helpers ----------------------------------------------------
__device__ __forceinline__ uint32_t smem_u32(const void* p) {
    uint32_t a;
    asm("{ .reg .u64 t; cvta.to.shared.u64 t, %1; cvt.u32.u64 %0, t; }" : "=r"(a) : "l"(p));
    return a;
}
__device__ __forceinline__ void cp16(uint32_t saddr, const void* g) {
    asm volatile("cp.async.cg.shared.global [%0], [%1], 16;" :: "r"(saddr), "l"(g) : "memory");
}
#define CP_COMMIT() asm volatile("cp.async.commit_group;" ::: "memory")

__device__ __forceinline__ void ldsm_x4(uint32_t& r0, uint32_t& r1, uint32_t& r2, uint32_t& r3,
                                        uint32_t addr) {
    asm volatile("ldmatrix.sync.aligned.m8n8.x4.shared.b16 {%0,%1,%2,%3}, [%4];"
                 : "=r"(r0), "=r"(r1), "=r"(r2), "=r"(r3) : "r"(addr));
}
__device__ __forceinline__ void ldsm_x2(uint32_t& r0, uint32_t& r1, uint32_t addr) {
    asm volatile("ldmatrix.sync.aligned.m8n8.x2.shared.b16 {%0,%1}, [%2];"
                 : "=r"(r0), "=r"(r1) : "r"(addr));
}
__device__ __forceinline__ void mma_bf16(float& c0, float& c1, float& c2, float& c3,
                                         uint32_t a0, uint32_t a1, uint32_t a2, uint32_t a3,
                                         uint32_t b0, uint32_t b1) {
    asm volatile("mma.sync.aligned.m16n8k16.row.col.f32.bf16.bf16.f32 "
                 "{%0,%1,%2,%3}, {%4,%5,%6,%7}, {%8,%9}, {%0,%1,%2,%3};"
                 : "+f"(c0), "+f"(c1), "+f"(c2), "+f"(c3)
                 : "r"(a0), "r"(a1), "r"(a2), "r"(a3), "r"(b0), "r"(b1));
}

// ---------------- small utils ------------------------------------------------
__global__ void zero_delta_kernel() {
    int i = blockIdx.x * blockDim.x + threadIdx.x;
    if (i < NTOK) g_dsum[i] = 0.f;
}

// ---------------- weight transpose+convert: src[R][C] f32 -> dst[C][R] bf16 --
__global__ __launch_bounds__(256) void wtrans_kernel(const float* __restrict__ src,
                                                     __nv_bfloat16* __restrict__ dst,
                                                     int R, int C) {
    __shared__ float t[32][33];
    int bx = blockIdx.x, by = blockIdx.y;
    int txi = threadIdx.x & 31, tyi = threadIdx.x >> 5;   // 32x8
    int x = bx * 32 + txi;
    int y0 = by * 32;
#pragma unroll
    for (int j = 0; j < 32; j += 8)
        t[tyi + j][txi] = src[(size_t)(y0 + tyi + j) * C + x];
    __syncthreads();
    int xo = by * 32 + txi;
    int yo0 = bx * 32;
#pragma unroll
    for (int j = 0; j < 32; j += 8)
        dst[(size_t)(yo0 + tyi + j) * R + xo] = __float2bfloat16_rn(t[txi][tyi + j]);
}

// ---------------- layernorm (writes bf16) ------------------------------------
__global__ __launch_bounds__(256) void ln_kernel(const float* __restrict__ x,
                                                 const float* __restrict__ gamma,
                                                 const float* __restrict__ beta) {
    int row = blockIdx.x;
    const float* xr = x + (size_t)row * DMODEL;
    float v[4];
    float s = 0.f, s2 = 0.f;
#pragma unroll
    for (int i = 0; i < 4; i++) {
        v[i] = xr[threadIdx.x + i * 256];
        s  += v[i];
        s2 += v[i] * v[i];
    }
    __shared__ float shs[8], shs2[8];
#pragma unroll
    for (int off = 16; off > 0; off >>= 1) {
        s  += __shfl_xor_sync(0xffffffffu, s,  off);
        s2 += __shfl_xor_sync(0xffffffffu, s2, off);
    }
    int warp = threadIdx.x >> 5, lane = threadIdx.x & 31;
    if (lane == 0) { shs[warp] = s; shs2[warp] = s2; }
    __syncthreads();
    if (threadIdx.x == 0) {
        float a = 0.f, b = 0.f;
#pragma unroll
        for (int w = 0; w < 8; w++) { a += shs[w]; b += shs2[w]; }
        shs[0] = a; shs2[0] = b;
    }
    __syncthreads();
    float mu  = shs[0]  * (1.f / DMODEL);
    float var = shs2[0] * (1.f / DMODEL) - mu * mu;
    float rs  = rsqrtf(var + 1e-5f);
    __nv_bfloat16* hr = g_hbf + (size_t)row * DMODEL;
#pragma unroll
    for (int i = 0; i < 4; i++) {
        int idx = threadIdx.x + i * 256;
        hr[idx] = __float2bfloat16_rn((v[i] - mu) * rs * gamma[idx] + beta[idx]);
    }
}

// ---------------- bf16 mma.sync GEMM -----------------------------------------
// Block 128x128, 8 warps (2x4), warp tile 64x32, K-chunk 64, cp.async double-buf.
// A [128][72] bf16 rows (pad 64->72), B (=W^T, [N][K] K-major) same layout.
// EPI 0: split cols -> g_xsbf / g_gatebf    EPI 1: softplus rowsum -> g_dsum
// EPI 2: C0 = acc + extra (fp32 residual), fp32 out
#define ASTR 72
#define TILE_B (128 * ASTR * 2)                 // 18432 bytes
#define GSMEM_BYTES (4 * TILE_B)                // 73728

template <int EPI>
__global__ __launch_bounds__(256) void mma_gemm(const __nv_bfloat16* __restrict__ A,
                                                const __nv_bfloat16* __restrict__ Bm,
                                                float* __restrict__ C0,
                                                const float* __restrict__ extra,
                                                const float* __restrict__ bias,
                                                int M, int N, int K) {
    extern __shared__ char dsm[];
    uint32_t sb = smem_u32(dsm);
    const uint32_t A0 = 0, A1 = TILE_B, B0 = 2 * TILE_B, B1 = 3 * TILE_B;

    int tid = threadIdx.x;
    int lane = tid & 31, wid = tid >> 5;
    int warp_m = wid & 1, warp_n = wid >> 1;
    int br = blockIdx.y, bc = blockIdx.x;

    const __nv_bfloat16* Ab = A + (size_t)(br * 128) * K;
    const __nv_bfloat16* Bb = Bm + (size_t)(bc * 128) * K;

    float acc[4][4][4];
#pragma unroll
    for (int mf = 0; mf < 4; mf++)
#pragma unroll
        for (int nf = 0; nf < 4; nf++)
#pragma unroll
            for (int j = 0; j < 4; j++) acc[mf][nf][j] = 0.f;

    int niter = K / 64;
    int c_row = tid >> 3, c_c = tid & 7;        // 128x8 tasks per 16B-chunk pass? (1024 tasks, 4/thread)

    // prologue
    {
#pragma unroll
        for (int i = 0; i < 4; i++) {
            int idx = tid + i * 256;
            int row = idx >> 3, c = idx & 7;
            cp16(sb + A0 + row * (ASTR * 2) + c * 16, Ab + (size_t)row * K + c * 8);
        }
#pragma unroll
        for (int i = 0; i < 4; i++) {
            int idx = tid + i * 256;
            int row = idx >> 3, c = idx & 7;
            cp16(sb + B0 + row * (ASTR * 2) + c * 16, Bb + (size_t)row * K + c * 8);
        }
        CP_COMMIT();
    }
    (void)c_row; (void)c_c;

    for (int it = 0; it < niter; ++it) {
        if (it + 1 < niter) {
            int nb = (it + 1) & 1;
            uint32_t sa = sb + (nb ? A1 : A0);
            uint32_t sbf = sb + (nb ? B1 : B0);
            int kk = (it + 1) * 64;
#pragma unroll
            for (int i = 0; i < 4; i++) {
                int idx = tid + i * 256;
                int row = idx >> 3, c = idx & 7;
                cp16(sa + row * (ASTR * 2) + c * 16, Ab + (size_t)row * K + kk + c * 8);
            }
#pragma unroll
            for (int i = 0; i < 4; i++) {
                int idx = tid + i * 256;
                int row = idx >> 3, c = idx & 7;
                cp16(sbf + row * (ASTR * 2) + c * 16, Bb + (size_t)row * K + kk + c * 8);
            }
            CP_COMMIT();
            asm volatile("cp.async.wait_group 1;" ::: "memory");
        } else {
            asm volatile("cp.async.wait_group 0;" ::: "memory");
        }
        __syncthreads();

        int cb = it & 1;
        uint32_t As = sb + (cb ? A1 : A0);
        uint32_t Bs = sb + (cb ? B1 : B0);

#pragma unroll
        for (int ks = 0; ks < 4; ks++) {
            int k0 = ks * 16;
            uint32_t afr[4][4];
#pragma unroll
            for (int mf = 0; mf < 4; mf++) {
                int r = warp_m * 64 + mf * 16 + (lane & 15);
                uint32_t ad = As + (r * ASTR + k0 + (lane >> 4) * 8) * 2;
                ldsm_x4(afr[mf][0], afr[mf][1], afr[mf][2], afr[mf][3], ad);
            }
            uint32_t bfr[4][2];
#pragma unroll
            for (int nf = 0; nf < 4; nf++) {
                int n = warp_n * 32 + nf * 8 + (lane & 7);
                uint32_t bd = Bs + (n * ASTR + k0 + ((lane >> 3) & 1) * 8) * 2;
                ldsm_x2(bfr[nf][0], bfr[nf][1], bd);
            }
#pragma unroll
            for (int mf = 0; mf < 4; mf++)
#pragma unroll
                for (int nf = 0; nf < 4; nf++)
                    mma_bf16(acc[mf][nf][0], acc[mf][nf][1], acc[mf][nf][2], acc[mf][nf][3],
                             afr[mf][0], afr[mf][1], afr[mf][2], afr[mf][3],
                             bfr[nf][0], bfr[nf][1]);
        }
        __syncthreads();
    }

    // -------- epilogue --------
    int g = lane >> 2, t4 = lane & 3;
#pragma unroll
    for (int mf = 0; mf < 4; mf++) {
        int row0 = br * 128 + warp_m * 64 + mf * 16 + g;
        if (EPI == 1) {
            float sum0 = 0.f, sum1 = 0.f;
#pragma unroll
            for (int nf = 0; nf < 4; nf++) {
                int col = bc * 128 + warp_n * 32 + nf * 8 + 2 * t4;
                float b0 = bias[col], b1 = bias[col + 1];
                float v;
                v = acc[mf][nf][0] + b0; sum0 += (v > 20.f) ? v : log1pf(expf(v));
                v = acc[mf][nf][1] + b1; sum0 += (v > 20.f) ? v : log1pf(expf(v));
                v = acc[mf][nf][2] + b0; sum1 += (v > 20.f) ? v : log1pf(expf(v));
                v = acc[mf][nf][3] + b1; sum1 += (v > 20.f) ? v : log1pf(expf(v));
            }
#pragma unroll
            for (int off = 1; off < 4; off <<= 1) {
                sum0 += __shfl_xor_sync(0xffffffffu, sum0, off);
                sum1 += __shfl_xor_sync(0xffffffffu, sum1, off);
            }
            if (t4 == 0) {
                atomicAdd(&g_dsum[row0], sum0);
                atomicAdd(&g_dsum[row0 + 8], sum1);
            }
        } else if (EPI == 0) {
            bool left = (bc * 128 < DINNER);
            __nv_bfloat16* dst = left ? g_xsbf : g_gatebf;
            int cbase = bc * 128 - (left ? 0 : DINNER) + warp_n * 32;
#pragma unroll
            for (int nf = 0; nf < 4; nf++) {
                int col = cbase + nf * 8 + 2 * t4;
                *(__nv_bfloat162*)(dst + (size_t)row0 * DINNER + col) =
                    __floats2bfloat162_rn(acc[mf][nf][0], acc[mf][nf][1]);
                *(__nv_bfloat162*)(dst + (size_t)(row0 + 8) * DINNER + col) =
                    __floats2bfloat162_rn(acc[mf][nf][2], acc[mf][nf][3]);
            }
        } else {
#pragma unroll
            for (int nf = 0; nf < 4; nf++) {
                int col = bc * 128 + warp_n * 32 + nf * 8 + 2 * t4;
                float2 e0 = *(const float2*)(extra + (size_t)row0 * N + col);
                float2 e1 = *(const float2*)(extra + (size_t)(row0 + 8) * N + col);
                *(float2*)(C0 + (size_t)row0 * N + col) =
                    make_float2(acc[mf][nf][0] + e0.x, acc[mf][nf][1] + e0.y);
                *(float2*)(C0 + (size_t)(row0 + 8) * N + col) =
                    make_float2(acc[mf][nf][2] + e1.x, acc[mf][nf][3] + e1.y);
            }
        }
    }
}

// ---------------- depthwise causal conv (K=4) + SiLU (bf16 in/out) ----------
__global__ __launch_bounds__(256) void conv_silu_kernel(const float* __restrict__ w,
                                                        const float* __restrict__ cb) {
    int id = blockIdx.x * 256 + threadIdx.x;
    int d = id & (DINNER - 1);
    int rest = id >> 11;
    int l = rest & (LSEQ - 1);
    int b = rest >> 11;
    const float* wr = w + d * KCONV;
    float v = cb[d];
#pragma unroll
    for (int k = 0; k < KCONV; k++) {
        int ll = l - (KCONV - 1) + k;
        float xv = (ll >= 0) ? __bfloat162float(g_xsbf[((size_t)(b * LSEQ + ll)) * DINNER + d]) : 0.f;
        v = fmaf(wr[k], xv, v);
    }
    g_xcbf[(size_t)id] = __float2bfloat16_rn(v / (1.f + expf(-v)));
}

// ---------------- Bx / dA ----------------------------------------------------
__global__ __launch_bounds__(256) void bx_kernel(const float* __restrict__ Bmat,
                                                 const float* __restrict__ A_log) {
    int t = blockIdx.x;
    const __nv_bfloat16* xrow = g_xcbf + (size_t)t * DINNER;
    float xr[8];
#pragma unroll
    for (int i = 0; i < 8; i++) xr[i] = __bfloat162float(xrow[threadIdx.x + i * 256]);

    float part[NSTATE];
#pragma unroll
    for (int n = 0; n < NSTATE; n++) {
        const float* Brow = Bmat + n * DINNER;
        float s = 0.f;
#pragma unroll
        for (int i = 0; i < 8; i++)
            s = fmaf(xr[i], Brow[threadIdx.x + i * 256], s);
        part[n] = s;
    }
#pragma unroll
    for (int n = 0; n < NSTATE; n++)
#pragma unroll
        for (int off = 16; off > 0; off >>= 1)
            part[n] += __shfl_xor_sync(0xffffffffu, part[n], off);

    __shared__ float sh[NSTATE][8];
    int warp = threadIdx.x >> 5, lane = threadIdx.x & 31;
    if (lane == 0)
#pragma unroll
        for (int n = 0; n < NSTATE; n++) sh[n][warp] = part[n];
    __syncthreads();

    if (threadIdx.x < NSTATE) {
        int n = threadIdx.x;
        float tot = 0.f;
#pragma unroll
        for (int w = 0; w < 8; w++) tot += sh[n][w];
        float delta = g_dsum[t] * (1.f / DINNER);
        float An = -expf(A_log[n]);
        g_dA[t * NSTATE + n] = expf(delta * An);
        g_Bx[t * NSTATE + n] = tot * delta;
    }
}

// ---------------- parallel linear-recurrence scan ----------------------------
__global__ __launch_bounds__(256) void scan_kernel() {
    int bn = blockIdx.x;
    int b = bn >> 4, n = bn & 15;
    size_t base = (size_t)b * LSEQ * NSTATE + n;
    int tid = threadIdx.x;
    int l0 = tid * 8;

    float av[8], bv[8];
#pragma unroll
    for (int i = 0; i < 8; i++) {
        av[i] = g_dA[base + (size_t)(l0 + i) * NSTATE];
        bv[i] = g_Bx[base + (size_t)(l0 + i) * NSTATE];
    }
    float aL = 1.f, bL = 0.f;
#pragma unroll
    for (int i = 0; i < 8; i++) { bL = fmaf(av[i], bL, bv[i]); aL *= av[i]; }

    __shared__ float sa[256], sbm[256];
    sa[tid] = aL; sbm[tid] = bL;
    __syncthreads();
#pragma unroll
    for (int off = 1; off < 256; off <<= 1) {
        float pa = 1.f, pb = 0.f;
        if (tid >= off) { pa = sa[tid - off]; pb = sbm[tid - off]; }
        float ca = sa[tid], cb2 = sbm[tid];
        __syncthreads();
        sa[tid] = pa * ca;
        sbm[tid] = fmaf(pb, ca, cb2);
        __syncthreads();
    }
    float h = (tid == 0) ? 0.f : sbm[tid - 1];
#pragma unroll
    for (int i = 0; i < 8; i++) {
        h = fmaf(av[i], h, bv[i]);
        g_hs[base + (size_t)(l0 + i) * NSTATE] = h;
    }
}

// ---------------- y = (hs@C^T + D*xc) * silu(gate) -> g_ybf ------------------
__global__ __launch_bounds__(256) void ymix_kernel(const float* __restrict__ Cmat,
                                                   const float* __restrict__ Dv) {
    int t = blockIdx.x;
    __shared__ float hsh[NSTATE];
    if (threadIdx.x < NSTATE) hsh[threadIdx.x] = g_hs[t * NSTATE + threadIdx.x];
    __syncthreads();

    for (int d = threadIdx.x; d < DINNER; d += 256) {
        const float4* cr = (const float4*)(Cmat + (size_t)d * NSTATE);
        float4 c0 = cr[0], c1 = cr[1], c2 = cr[2], c3 = cr[3];
        float s = 0.f;
        s = fmaf(hsh[0],  c0.x, s); s = fmaf(hsh[1],  c0.y, s);
        s = fmaf(hsh[2],  c0.z, s); s = fmaf(hsh[3],  c0.w, s);
        s = fmaf(hsh[4],  c1.x, s); s = fmaf(hsh[5],  c1.y, s);
        s = fmaf(hsh[6],  c1.z, s); s = fmaf(hsh[7],  c1.w, s);
        s = fmaf(hsh[8],  c2.x, s); s = fmaf(hsh[9],  c2.y, s);
        s = fmaf(hsh[10], c2.z, s); s = fmaf(hsh[11], c2.w, s);
        s = fmaf(hsh[12], c3.x, s); s = fmaf(hsh[13], c3.y, s);
        s = fmaf(hsh[14], c3.z, s); s = fmaf(hsh[15], c3.w, s);
        size_t idx = (size_t)t * DINNER + d;
        float xv = __bfloat162float(g_xcbf[idx]);
        float yv = fmaf(Dv[d], xv, s);
        float gg = __bfloat162float(g_gatebf[idx]);
        yv *= gg / (1.f + expf(-gg));
        g_ybf[idx] = __float2bfloat16_rn(yv);
    }
}

// ---------------- launch -----------------------------------------------------
extern "C" void kernel_launch(void* const* d_in, const int* in_sizes, int n_in,
                              void* d_out, int out_size) {
    const float* x       = (const float*)d_in[0];
    const float* ln_g    = (const float*)d_in[1];
    const float* ln_b    = (const float*)d_in[2];
    const float* W_in    = (const float*)d_in[3];
    const float* conv_w  = (const float*)d_in[4];
    const float* conv_b  = (const float*)d_in[5];
    const float* A_log   = (const float*)d_in[6];
    const float* B_mat   = (const float*)d_in[7];
    const float* C_mat   = (const float*)d_in[8];
    const float* D_vec   = (const float*)d_in[9];
    const float* Wd      = (const float*)d_in[10];
    const float* bd      = (const float*)d_in[11];
    const float* W_out   = (const float*)d_in[12];
    float* out           = (float*)d_out;

    __nv_bfloat16 *hbf, *xcbf, *ybf, *wint, *wdt, *woutt;
    cudaGetSymbolAddress((void**)&hbf,   g_hbf);
    cudaGetSymbolAddress((void**)&xcbf,  g_xcbf);
    cudaGetSymbolAddress((void**)&ybf,   g_ybf);
    cudaGetSymbolAddress((void**)&wint,  g_Wint);
    cudaGetSymbolAddress((void**)&wdt,   g_Wdt);
    cudaGetSymbolAddress((void**)&woutt, g_Woutt);

    cudaFuncSetAttribute(mma_gemm<0>, cudaFuncAttributeMaxDynamicSharedMemorySize, GSMEM_BYTES);
    cudaFuncSetAttribute(mma_gemm<1>, cudaFuncAttributeMaxDynamicSharedMemorySize, GSMEM_BYTES);
    cudaFuncSetAttribute(mma_gemm<2>, cudaFuncAttributeMaxDynamicSharedMemorySize, GSMEM_BYTES);

    zero_delta_kernel<<<16, 256>>>();
    // weight transpose+convert (f32 [R][C] -> bf16 [C][R])
    wtrans_kernel<<<dim3(2 * DINNER / 32, DMODEL / 32), 256>>>(W_in, wint, DMODEL, 2 * DINNER);
    wtrans_kernel<<<dim3(DINNER / 32, DINNER / 32), 256>>>(Wd, wdt, DINNER, DINNER);
    wtrans_kernel<<<dim3(DMODEL / 32, DINNER / 32), 256>>>(W_out, woutt, DINNER, DMODEL);
    ln_kernel<<<NTOK, 256>>>(x, ln_g, ln_b);
    // GEMM1: h(4096x1024) @ W_in -> xs | gate (bf16)
    mma_gemm<0><<<dim3(32, 32), 256, GSMEM_BYTES>>>(hbf, wint, nullptr, nullptr, nullptr,
                                                    NTOK, 2 * DINNER, DMODEL);
    conv_silu_kernel<<<(NTOK * DINNER) / 256, 256>>>(conv_w, conv_b);
    // GEMM2: xc(4096x2048) @ Wd, softplus row-sum epilogue
    mma_gemm<1><<<dim3(16, 32), 256, GSMEM_BYTES>>>(xcbf, wdt, nullptr, nullptr, bd,
                                                    NTOK, DINNER, DINNER);
    bx_kernel<<<NTOK, 256>>>(B_mat, A_log);
    scan_kernel<<<BSZ * NSTATE, 256>>>();
    ymix_kernel<<<NTOK, 256>>>(C_mat, D_vec);
    // GEMM3: y(4096x2048) @ W_out + residual -> out (fp32)
    mma_gemm<2><<<dim3(8, 32), 256, GSMEM_BYTES>>>(ybf, woutt, out, x, nullptr,
                                                   NTOK, DMODEL, DINNER);
}

// round 5
// speedup vs baseline: 4.8702x; 1.0009x over previous
#include <cuda_runtime.h>
#include <cuda_bf16.h>
#include <math.h>
#include <stdint.h>

#define BSZ     2
#define LSEQ    2048
#define DMODEL  1024
#define DINNER  2048
#define NSTATE  16
#define KCONV   4
#define NTOK    (BSZ*LSEQ)   // 4096

// ---------------- scratch (static device globals; no allocation) -------------
__device__ __align__(256) __nv_bfloat16 g_hbf   [NTOK*DMODEL];
__device__ __align__(256) __nv_bfloat16 g_xsbf  [NTOK*DINNER];
__device__ __align__(256) __nv_bfloat16 g_gatebf[NTOK*DINNER];
__device__ __align__(256) __nv_bfloat16 g_xcbf  [NTOK*DINNER];
__device__ __align__(256) __nv_bfloat16 g_ybf   [NTOK*DINNER];
__device__ __align__(256) __nv_bfloat16 g_Wint  [(2*DINNER)*DMODEL];
__device__ __align__(256) __nv_bfloat16 g_Wdt   [DINNER*DINNER];
__device__ __align__(256) __nv_bfloat16 g_Woutt [DMODEL*DINNER];
__device__ __align__(256) __nv_bfloat16 g_Bbf   [NSTATE*DINNER];
__device__ float g_dsum[NTOK];
__device__ float g_dA  [NTOK*NSTATE];
__device__ float g_Bx  [NTOK*NSTATE];
__device__ float g_hs  [NTOK*NSTATE];

// ---------------- helpers ----------------------------------------------------
__device__ __forceinline__ uint32_t smem_u32(const void* p) {
    uint32_t a;
    asm("{ .reg .u64 t; cvta.to.shared.u64 t, %1; cvt.u32.u64 %0, t; }" : "=r"(a) : "l"(p));
    return a;
}
__device__ __forceinline__ void cp16(uint32_t saddr, const void* g) {
    asm volatile("cp.async.cg.shared.global [%0], [%1], 16;" :: "r"(saddr), "l"(g) : "memory");
}
#define CP_COMMIT() asm volatile("cp.async.commit_group;" ::: "memory")

__device__ __forceinline__ void ldsm_x4(uint32_t& r0, uint32_t& r1, uint32_t& r2, uint32_t& r3,
                                        uint32_t addr) {
    asm volatile("ldmatrix.sync.aligned.m8n8.x4.shared.b16 {%0,%1,%2,%3}, [%4];"
                 : "=r"(r0), "=r"(r1), "=r"(r2), "=r"(r3) : "r"(addr));
}
__device__ __forceinline__ void mma_bf16(float& c0, float& c1, float& c2, float& c3,
                                         uint32_t a0, uint32_t a1, uint32_t a2, uint32_t a3,
                                         uint32_t b0, uint32_t b1) {
    asm volatile("mma.sync.aligned.m16n8k16.row.col.f32.bf16.bf16.f32 "
                 "{%0,%1,%2,%3}, {%4,%5,%6,%7}, {%8,%9}, {%0,%1,%2,%3};"
                 : "+f"(c0), "+f"(c1), "+f"(c2), "+f"(c3)
                 : "r"(a0), "r"(a1), "r"(a2), "r"(a3), "r"(b0), "r"(b1));
}

// ---------------- small utils ------------------------------------------------
__global__ void zero_delta_kernel() {
    int i = blockIdx.x * blockDim.x + threadIdx.x;
    if (i < NTOK) g_dsum[i] = 0.f;
}

// B_mat f32 -> bf16 (same layout)
__global__ void bconv_kernel(const float* __restrict__ src) {
    int i = blockIdx.x * 256 + threadIdx.x;   // over NSTATE*DINNER/2
    float2 v = *(const float2*)(src + 2 * i);
    *(__nv_bfloat162*)(g_Bbf + 2 * i) = __floats2bfloat162_rn(v.x, v.y);
}

// ---------------- weight transpose+convert: src[R][C] f32 -> dst[C][R] bf16 --
__global__ __launch_bounds__(256) void wtrans_kernel(const float* __restrict__ src,
                                                     __nv_bfloat16* __restrict__ dst,
                                                     int R, int C) {
    __shared__ float t[32][33];
    int bx = blockIdx.x, by = blockIdx.y;
    int txi = threadIdx.x & 31, tyi = threadIdx.x >> 5;
    int x = bx * 32 + txi;
    int y0 = by * 32;
#pragma unroll
    for (int j = 0; j < 32; j += 8)
        t[tyi + j][txi] = src[(size_t)(y0 + tyi + j) * C + x];
    __syncthreads();
    int xo = by * 32 + txi;
    int yo0 = bx * 32;
#pragma unroll
    for (int j = 0; j < 32; j += 8)
        dst[(size_t)(yo0 + tyi + j) * R + xo] = __float2bfloat16_rn(t[txi][tyi + j]);
}

// ---------------- layernorm (writes bf16) ------------------------------------
__global__ __launch_bounds__(256) void ln_kernel(const float* __restrict__ x,
                                                 const float* __restrict__ gamma,
                                                 const float* __restrict__ beta) {
    int row = blockIdx.x;
    const float* xr = x + (size_t)row * DMODEL;
    float v[4];
    float s = 0.f, s2 = 0.f;
#pragma unroll
    for (int i = 0; i < 4; i++) {
        v[i] = xr[threadIdx.x + i * 256];
        s  += v[i];
        s2 += v[i] * v[i];
    }
    __shared__ float shs[8], shs2[8];
#pragma unroll
    for (int off = 16; off > 0; off >>= 1) {
        s  += __shfl_xor_sync(0xffffffffu, s,  off);
        s2 += __shfl_xor_sync(0xffffffffu, s2, off);
    }
    int warp = threadIdx.x >> 5, lane = threadIdx.x & 31;
    if (lane == 0) { shs[warp] = s; shs2[warp] = s2; }
    __syncthreads();
    if (threadIdx.x == 0) {
        float a = 0.f, b = 0.f;
#pragma unroll
        for (int w = 0; w < 8; w++) { a += shs[w]; b += shs2[w]; }
        shs[0] = a; shs2[0] = b;
    }
    __syncthreads();
    float mu  = shs[0]  * (1.f / DMODEL);
    float var = shs2[0] * (1.f / DMODEL) - mu * mu;
    float rs  = rsqrtf(var + 1e-5f);
    __nv_bfloat16* hr = g_hbf + (size_t)row * DMODEL;
#pragma unroll
    for (int i = 0; i < 4; i++) {
        int idx = threadIdx.x + i * 256;
        hr[idx] = __float2bfloat16_rn((v[i] - mu) * rs * gamma[idx] + beta[idx]);
    }
}

// ---------------- bf16 mma.sync GEMM, 3-stage pipeline -----------------------
// Block 128x128, 8 warps (2x4), warp tile 64x32, K-chunk 64.
#define ASTR 72
#define TILE_B (128 * ASTR * 2)                 // 18432 bytes per operand stage
#define GSMEM_BYTES (6 * TILE_B)                // 110592

template <int EPI>
__global__ __launch_bounds__(256) void mma_gemm(const __nv_bfloat16* __restrict__ A,
                                                const __nv_bfloat16* __restrict__ Bm,
                                                float* __restrict__ C0,
                                                const float* __restrict__ extra,
                                                const float* __restrict__ bias,
                                                int M, int N, int K) {
    extern __shared__ char dsm[];
    uint32_t sb = smem_u32(dsm);

    int tid = threadIdx.x;
    int lane = tid & 31, wid = tid >> 5;
    int warp_m = wid & 1, warp_n = wid >> 1;
    int br = blockIdx.y, bc = blockIdx.x;

    const __nv_bfloat16* Ab = A + (size_t)(br * 128) * K;
    const __nv_bfloat16* Bb = Bm + (size_t)(bc * 128) * K;

    float acc[4][4][4];
#pragma unroll
    for (int mf = 0; mf < 4; mf++)
#pragma unroll
        for (int nf = 0; nf < 4; nf++)
#pragma unroll
            for (int j = 0; j < 4; j++) acc[mf][nf][j] = 0.f;

    int niter = K / 64;
    int c_row = tid >> 1;                        // unused placeholder
    (void)c_row;

    // stage buffers: A at stage*TILE_B, B at (3+stage)*TILE_B
    // prologue: stages 0,1
#pragma unroll
    for (int st = 0; st < 2; ++st) {
        uint32_t sa = sb + st * TILE_B;
        uint32_t sbf = sb + (3 + st) * TILE_B;
        int kk = st * 64;
#pragma unroll
        for (int i = 0; i < 4; i++) {
            int idx = tid + i * 256;
            int row = idx >> 3, c = idx & 7;
            cp16(sa + row * (ASTR * 2) + c * 16, Ab + (size_t)row * K + kk + c * 8);
        }
#pragma unroll
        for (int i = 0; i < 4; i++) {
            int idx = tid + i * 256;
            int row = idx >> 3, c = idx & 7;
            cp16(sbf + row * (ASTR * 2) + c * 16, Bb + (size_t)row * K + kk + c * 8);
        }
        CP_COMMIT();
    }

    for (int it = 0; it < niter; ++it) {
        if (it + 2 < niter)
            asm volatile("cp.async.wait_group 1;" ::: "memory");
        else
            asm volatile("cp.async.wait_group 0;" ::: "memory");
        __syncthreads();

        // prefetch stage it+2
        if (it + 2 < niter) {
            int st = (it + 2) % 3;
            uint32_t sa = sb + st * TILE_B;
            uint32_t sbf = sb + (3 + st) * TILE_B;
            int kk = (it + 2) * 64;
#pragma unroll
            for (int i = 0; i < 4; i++) {
                int idx = tid + i * 256;
                int row = idx >> 3, c = idx & 7;
                cp16(sa + row * (ASTR * 2) + c * 16, Ab + (size_t)row * K + kk + c * 8);
            }
#pragma unroll
            for (int i = 0; i < 4; i++) {
                int idx = tid + i * 256;
                int row = idx >> 3, c = idx & 7;
                cp16(sbf + row * (ASTR * 2) + c * 16, Bb + (size_t)row * K + kk + c * 8);
            }
            CP_COMMIT();
        }

        int st = it % 3;
        uint32_t As = sb + st * TILE_B;
        uint32_t Bs = sb + (3 + st) * TILE_B;

#pragma unroll
        for (int ks = 0; ks < 4; ks++) {
            int k0 = ks * 16;
            uint32_t afr[4][4];
#pragma unroll
            for (int mf = 0; mf < 4; mf++) {
                int r = warp_m * 64 + mf * 16 + (lane & 15);
                uint32_t ad = As + (r * ASTR + k0 + (lane >> 4) * 8) * 2;
                ldsm_x4(afr[mf][0], afr[mf][1], afr[mf][2], afr[mf][3], ad);
            }
            uint32_t bfr[4][2];
#pragma unroll
            for (int nfp = 0; nfp < 2; nfp++) {
                // x4 loads 16 cols x k16: m0=(c0..c0+7,k0) m1=(.,k8) m2=(c0+8..,k0) m3=(.,k8)
                int gsel = lane >> 3, rr = lane & 7;
                int n = warp_n * 32 + nfp * 16 + (gsel >> 1) * 8 + rr;
                int ko = k0 + (gsel & 1) * 8;
                uint32_t bd = Bs + (n * ASTR + ko) * 2;
                ldsm_x4(bfr[2 * nfp][0], bfr[2 * nfp][1],
                        bfr[2 * nfp + 1][0], bfr[2 * nfp + 1][1], bd);
            }
#pragma unroll
            for (int mf = 0; mf < 4; mf++)
#pragma unroll
                for (int nf = 0; nf < 4; nf++)
                    mma_bf16(acc[mf][nf][0], acc[mf][nf][1], acc[mf][nf][2], acc[mf][nf][3],
                             afr[mf][0], afr[mf][1], afr[mf][2], afr[mf][3],
                             bfr[nf][0], bfr[nf][1]);
        }
    }

    // -------- epilogue --------
    int g = lane >> 2, t4 = lane & 3;
#pragma unroll
    for (int mf = 0; mf < 4; mf++) {
        int row0 = br * 128 + warp_m * 64 + mf * 16 + g;
        if (EPI == 1) {
            float sum0 = 0.f, sum1 = 0.f;
#pragma unroll
            for (int nf = 0; nf < 4; nf++) {
                int col = bc * 128 + warp_n * 32 + nf * 8 + 2 * t4;
                float b0 = bias[col], b1 = bias[col + 1];
                float v;
                v = acc[mf][nf][0] + b0; sum0 += (v > 20.f) ? v : log1pf(expf(v));
                v = acc[mf][nf][1] + b1; sum0 += (v > 20.f) ? v : log1pf(expf(v));
                v = acc[mf][nf][2] + b0; sum1 += (v > 20.f) ? v : log1pf(expf(v));
                v = acc[mf][nf][3] + b1; sum1 += (v > 20.f) ? v : log1pf(expf(v));
            }
#pragma unroll
            for (int off = 1; off < 4; off <<= 1) {
                sum0 += __shfl_xor_sync(0xffffffffu, sum0, off);
                sum1 += __shfl_xor_sync(0xffffffffu, sum1, off);
            }
            if (t4 == 0) {
                atomicAdd(&g_dsum[row0], sum0);
                atomicAdd(&g_dsum[row0 + 8], sum1);
            }
        } else if (EPI == 0) {
            bool left = (bc * 128 < DINNER);
            __nv_bfloat16* dst = left ? g_xsbf : g_gatebf;
            int cbase = bc * 128 - (left ? 0 : DINNER) + warp_n * 32;
#pragma unroll
            for (int nf = 0; nf < 4; nf++) {
                int col = cbase + nf * 8 + 2 * t4;
                *(__nv_bfloat162*)(dst + (size_t)row0 * DINNER + col) =
                    __floats2bfloat162_rn(acc[mf][nf][0], acc[mf][nf][1]);
                *(__nv_bfloat162*)(dst + (size_t)(row0 + 8) * DINNER + col) =
                    __floats2bfloat162_rn(acc[mf][nf][2], acc[mf][nf][3]);
            }
        } else {
#pragma unroll
            for (int nf = 0; nf < 4; nf++) {
                int col = bc * 128 + warp_n * 32 + nf * 8 + 2 * t4;
                float2 e0 = *(const float2*)(extra + (size_t)row0 * N + col);
                float2 e1 = *(const float2*)(extra + (size_t)(row0 + 8) * N + col);
                *(float2*)(C0 + (size_t)row0 * N + col) =
                    make_float2(acc[mf][nf][0] + e0.x, acc[mf][nf][1] + e0.y);
                *(float2*)(C0 + (size_t)(row0 + 8) * N + col) =
                    make_float2(acc[mf][nf][2] + e1.x, acc[mf][nf][3] + e1.y);
            }
        }
    }
}

// ---------------- depthwise causal conv (K=4) + SiLU, 2-wide ----------------
__global__ __launch_bounds__(256) void conv_silu_kernel(const float* __restrict__ w,
                                                        const float* __restrict__ cb) {
    int id2 = blockIdx.x * 256 + threadIdx.x;          // over NTOK*DINNER/2
    int d2 = id2 & (DINNER / 2 - 1);                   // pair index
    int rest = id2 >> 10;
    int l = rest & (LSEQ - 1);
    int b = rest >> 11;
    int d = d2 * 2;
    float4 w0 = *(const float4*)(w + d * KCONV);       // weights for d
    float4 w1 = *(const float4*)(w + (d + 1) * KCONV); // weights for d+1
    float2 bb = *(const float2*)(cb + d);
    float v0 = bb.x, v1 = bb.y;
    const float wa[2][4] = {{w0.x, w0.y, w0.z, w0.w}, {w1.x, w1.y, w1.z, w1.w}};
#pragma unroll
    for (int k = 0; k < KCONV; k++) {
        int ll = l - (KCONV - 1) + k;
        float x0 = 0.f, x1 = 0.f;
        if (ll >= 0) {
            __nv_bfloat162 xv = *(const __nv_bfloat162*)(g_xsbf + ((size_t)(b * LSEQ + ll)) * DINNER + d);
            x0 = __bfloat162float(xv.x);
            x1 = __bfloat162float(xv.y);
        }
        v0 = fmaf(wa[0][k], x0, v0);
        v1 = fmaf(wa[1][k], x1, v1);
    }
    float s0 = v0 / (1.f + expf(-v0));
    float s1 = v1 / (1.f + expf(-v1));
    *(__nv_bfloat162*)(g_xcbf + (size_t)(b * LSEQ + l) * DINNER + d) = __floats2bfloat162_rn(s0, s1);
}

// ---------------- Bx / dA: 4 tokens per block, bf16 B ------------------------
#define BX_TB 4
__global__ __launch_bounds__(256) void bx_kernel(const float* __restrict__ A_log) {
    int t0 = blockIdx.x * BX_TB;
    int tid = threadIdx.x;
    float xr[BX_TB][8];
#pragma unroll
    for (int t = 0; t < BX_TB; t++) {
        const __nv_bfloat16* xrow = g_xcbf + (size_t)(t0 + t) * DINNER;
#pragma unroll
        for (int i = 0; i < 8; i++)
            xr[t][i] = __bfloat162float(xrow[tid + i * 256]);
    }
    __shared__ float sh[NSTATE][BX_TB][8];
    int warp = tid >> 5, lane = tid & 31;
#pragma unroll
    for (int n = 0; n < NSTATE; n++) {
        const __nv_bfloat16* Brow = g_Bbf + n * DINNER;
        float bvv[8];
#pragma unroll
        for (int i = 0; i < 8; i++) bvv[i] = __bfloat162float(Brow[tid + i * 256]);
        float part[BX_TB];
#pragma unroll
        for (int t = 0; t < BX_TB; t++) {
            float s = 0.f;
#pragma unroll
            for (int i = 0; i < 8; i++) s = fmaf(xr[t][i], bvv[i], s);
            part[t] = s;
        }
#pragma unroll
        for (int t = 0; t < BX_TB; t++)
#pragma unroll
            for (int off = 16; off > 0; off >>= 1)
                part[t] += __shfl_xor_sync(0xffffffffu, part[t], off);
        if (lane == 0)
#pragma unroll
            for (int t = 0; t < BX_TB; t++) sh[n][t][warp] = part[t];
    }
    __syncthreads();
    if (tid < NSTATE * BX_TB) {
        int n = tid & 15, t = tid >> 4;
        float tot = 0.f;
#pragma unroll
        for (int w = 0; w < 8; w++) tot += sh[n][t][w];
        int tok = t0 + t;
        float delta = g_dsum[tok] * (1.f / DINNER);
        float An = -expf(A_log[n]);
        g_dA[tok * NSTATE + n] = expf(delta * An);
        g_Bx[tok * NSTATE + n] = tot * delta;
    }
}

// ---------------- parallel linear-recurrence scan ----------------------------
__global__ __launch_bounds__(256) void scan_kernel() {
    int bn = blockIdx.x;
    int b = bn >> 4, n = bn & 15;
    size_t base = (size_t)b * LSEQ * NSTATE + n;
    int tid = threadIdx.x;
    int l0 = tid * 8;

    float av[8], bv[8];
#pragma unroll
    for (int i = 0; i < 8; i++) {
        av[i] = g_dA[base + (size_t)(l0 + i) * NSTATE];
        bv[i] = g_Bx[base + (size_t)(l0 + i) * NSTATE];
    }
    float aL = 1.f, bL = 0.f;
#pragma unroll
    for (int i = 0; i < 8; i++) { bL = fmaf(av[i], bL, bv[i]); aL *= av[i]; }

    __shared__ float sa[256], sbm[256];
    sa[tid] = aL; sbm[tid] = bL;
    __syncthreads();
#pragma unroll
    for (int off = 1; off < 256; off <<= 1) {
        float pa = 1.f, pb = 0.f;
        if (tid >= off) { pa = sa[tid - off]; pb = sbm[tid - off]; }
        float ca = sa[tid], cb2 = sbm[tid];
        __syncthreads();
        sa[tid] = pa * ca;
        sbm[tid] = fmaf(pb, ca, cb2);
        __syncthreads();
    }
    float h = (tid == 0) ? 0.f : sbm[tid - 1];
#pragma unroll
    for (int i = 0; i < 8; i++) {
        h = fmaf(av[i], h, bv[i]);
        g_hs[base + (size_t)(l0 + i) * NSTATE] = h;
    }
}

// ---------------- y = (hs@C^T + D*xc) * silu(gate), 8 tokens/block -----------
#define YM_TB 8
__global__ __launch_bounds__(256) void ymix_kernel(const float* __restrict__ Cmat,
                                                   const float* __restrict__ Dv) {
    int t0 = blockIdx.x * YM_TB;
    __shared__ float hsh[YM_TB][NSTATE];
    if (threadIdx.x < YM_TB * NSTATE) {
        int t = threadIdx.x >> 4, n = threadIdx.x & 15;
        hsh[t][n] = g_hs[(t0 + t) * NSTATE + n];
    }
    __syncthreads();

    for (int d = threadIdx.x; d < DINNER; d += 256) {
        const float4* cr = (const float4*)(Cmat + (size_t)d * NSTATE);
        float4 c0 = cr[0], c1 = cr[1], c2 = cr[2], c3 = cr[3];
        float dvd = Dv[d];
#pragma unroll
        for (int t = 0; t < YM_TB; t++) {
            const float* hh = hsh[t];
            float s = 0.f;
            s = fmaf(hh[0],  c0.x, s); s = fmaf(hh[1],  c0.y, s);
            s = fmaf(hh[2],  c0.z, s); s = fmaf(hh[3],  c0.w, s);
            s = fmaf(hh[4],  c1.x, s); s = fmaf(hh[5],  c1.y, s);
            s = fmaf(hh[6],  c1.z, s); s = fmaf(hh[7],  c1.w, s);
            s = fmaf(hh[8],  c2.x, s); s = fmaf(hh[9],  c2.y, s);
            s = fmaf(hh[10], c2.z, s); s = fmaf(hh[11], c2.w, s);
            s = fmaf(hh[12], c3.x, s); s = fmaf(hh[13], c3.y, s);
            s = fmaf(hh[14], c3.z, s); s = fmaf(hh[15], c3.w, s);
            size_t idx = (size_t)(t0 + t) * DINNER + d;
            float xv = __bfloat162float(g_xcbf[idx]);
            float yv = fmaf(dvd, xv, s);
            float gg = __bfloat162float(g_gatebf[idx]);
            yv *= gg / (1.f + expf(-gg));
            g_ybf[idx] = __float2bfloat16_rn(yv);
        }
    }
}

// ---------------- launch -----------------------------------------------------
extern "C" void kernel_launch(void* const* d_in, const int* in_sizes, int n_in,
                              void* d_out, int out_size) {
    const float* x       = (const float*)d_in[0];
    const float* ln_g    = (const float*)d_in[1];
    const float* ln_b    = (const float*)d_in[2];
    const float* W_in    = (const float*)d_in[3];
    const float* conv_w  = (const float*)d_in[4];
    const float* conv_b  = (const float*)d_in[5];
    const float* A_log   = (const float*)d_in[6];
    const float* B_mat   = (const float*)d_in[7];
    const float* C_mat   = (const float*)d_in[8];
    const float* D_vec   = (const float*)d_in[9];
    const float* Wd      = (const float*)d_in[10];
    const float* bd      = (const float*)d_in[11];
    const float* W_out   = (const float*)d_in[12];
    float* out           = (float*)d_out;

    __nv_bfloat16 *hbf, *ybf, *wint, *wdt, *woutt;
    cudaGetSymbolAddress((void**)&hbf,   g_hbf);
    cudaGetSymbolAddress((void**)&ybf,   g_ybf);
    cudaGetSymbolAddress((void**)&wint,  g_Wint);
    cudaGetSymbolAddress((void**)&wdt,   g_Wdt);
    cudaGetSymbolAddress((void**)&woutt, g_Woutt);
    __nv_bfloat16* xcbf;
    cudaGetSymbolAddress((void**)&xcbf,  g_xcbf);

    cudaFuncSetAttribute(mma_gemm<0>, cudaFuncAttributeMaxDynamicSharedMemorySize, GSMEM_BYTES);
    cudaFuncSetAttribute(mma_gemm<1>, cudaFuncAttributeMaxDynamicSharedMemorySize, GSMEM_BYTES);
    cudaFuncSetAttribute(mma_gemm<2>, cudaFuncAttributeMaxDynamicSharedMemorySize, GSMEM_BYTES);

    zero_delta_kernel<<<16, 256>>>();
    bconv_kernel<<<(NSTATE * DINNER / 2) / 256, 256>>>(B_mat);
    wtrans_kernel<<<dim3(2 * DINNER / 32, DMODEL / 32), 256>>>(W_in, wint, DMODEL, 2 * DINNER);
    wtrans_kernel<<<dim3(DINNER / 32, DINNER / 32), 256>>>(Wd, wdt, DINNER, DINNER);
    wtrans_kernel<<<dim3(DMODEL / 32, DINNER / 32), 256>>>(W_out, woutt, DINNER, DMODEL);
    ln_kernel<<<NTOK, 256>>>(x, ln_g, ln_b);
    mma_gemm<0><<<dim3(32, 32), 256, GSMEM_BYTES>>>(hbf, wint, nullptr, nullptr, nullptr,
                                                    NTOK, 2 * DINNER, DMODEL);
    conv_silu_kernel<<<(NTOK * DINNER / 2) / 256, 256>>>(conv_w, conv_b);
    mma_gemm<1><<<dim3(16, 32), 256, GSMEM_BYTES>>>(xcbf, wdt, nullptr, nullptr, bd,
                                                    NTOK, DINNER, DINNER);
    bx_kernel<<<NTOK / BX_TB, 256>>>(A_log);
    scan_kernel<<<BSZ * NSTATE, 256>>>();
    ymix_kernel<<<NTOK / YM_TB, 256>>>(C_mat, D_vec);
    mma_gemm<2><<<dim3(8, 32), 256, GSMEM_BYTES>>>(ybf, woutt, out, x, nullptr,
                                                   NTOK, DMODEL, DINNER);
}